// round 4
// baseline (speedup 1.0000x reference)
#include <cuda_runtime.h>
#include <cuda_bf16.h>
#include <mma.h>

using namespace nvcuda;

// Problem constants
#define GB   2        // batch
#define GN   256      // num anchor blocks
#define GL   4        // layers
#define GS   4096     // seq len
#define GH   2048     // hidden
#define NH   16       // heads
#define DH   128      // head dim
#define BSQ  16       // block size (queries per anchor block)
#define NHD  2048     // NH*DH
#define MM   2048     // B*N*L rows of context GEMM
#define KNN  4096     // concat output cols (Wkc | Wvc)
#define SCALE 0.08838834764831845f  // 1/sqrt(128)

// Scratch: context GEMM output  C[m, 0:2048] = k_chs, C[m, 2048:4096] = v_chs
__device__ float g_C[(size_t)MM * KNN];

// Read anchor value regardless of whether the harness stored int32 or int64.
__device__ __forceinline__ bool anchor_is_i64(const void* anchor) {
    const long long* a64 = (const long long*)anchor;
    bool ok = true;
    #pragma unroll
    for (int i = 0; i < 4; i++) {
        long long t = a64[i];
        if (t < 0 || t >= GS) ok = false;
    }
    return ok;
}

__device__ __forceinline__ long long anchor_read(const void* anchor, int idx, bool is64) {
    if (is64) return ((const long long*)anchor)[idx];
    return (long long)((const int*)anchor)[idx];
}

// ---------------------------------------------------------------------------
// Kernel 1: gathered tf32 GEMM
//   A[m,k] = hidden_states[l, b, ctx(b,n), k]  with m = ((b*N+n)*L + l)
//   Bmat   = [W_kc | W_vc]  (2048 x 4096), row-major
//   C      = A @ Bmat   (2048 x 4096)
// Tile: BM=64, BN=128, BK=16; 8 warps, each computes 32x32 via 2x2 wmma tiles.
// ---------------------------------------------------------------------------
__global__ __launch_bounds__(256) void gemm_ctx_kernel(
    const float* __restrict__ hidden,
    const void* __restrict__ anchor,
    const float* __restrict__ Wkc,
    const float* __restrict__ Wvc)
{
    const int bx = blockIdx.x;   // output-col tile (128 wide): 0..31
    const int by = blockIdx.y;   // output-row tile (64 tall):  0..31
    const int tid = threadIdx.x;

    __shared__ float  As[64][24];     // stride 24 (mult of 8, 16B-aligned rows)
    __shared__ float  Bs[16][136];    // stride 136 (mult of 8)
    __shared__ size_t rowbase[64];

    if (tid < 64) {
        const bool is64 = anchor_is_i64(anchor);
        int m  = by * 64 + tid;
        int l  = m & 3;
        int bn = m >> 2;
        int b  = bn >> 8;
        int n  = bn & 255;
        long long a = anchor_read(anchor, b * GN + n, is64) - 1;
        if (a < 0) a = 0;
        if (a > GS - 1) a = GS - 1;   // defensive clamp: never OOB
        rowbase[tid] = (((size_t)l * GB + b) * GS + (size_t)a) * GH;
    }

    // A whole 128-wide col tile lives entirely in Wkc (bx<16) or Wvc.
    const float* Wbase = (bx < 16) ? (Wkc + bx * 128) : (Wvc + (bx - 16) * 128);

    wmma::fragment<wmma::accumulator, 16, 16, 8, float> acc[2][2];
    #pragma unroll
    for (int i = 0; i < 2; i++)
        #pragma unroll
        for (int j = 0; j < 2; j++)
            wmma::fill_fragment(acc[i][j], 0.0f);

    const int warp = tid >> 5;
    const int wm = warp & 1;      // 0..1 -> 32-row slice
    const int wn = warp >> 1;     // 0..3 -> 32-col slice

    __syncthreads();

    const int arow = tid >> 2;
    const int ac4  = (tid & 3) << 2;

    for (int k0 = 0; k0 < GH; k0 += 16) {
        // Load A tile: 64 rows x 16 cols, one float4 per thread (gathered rows)
        float4 av = *reinterpret_cast<const float4*>(hidden + rowbase[arow] + k0 + ac4);
        *reinterpret_cast<float4*>(&As[arow][ac4]) = av;

        // Load B tile: 16 rows x 128 cols, two float4 per thread
        #pragma unroll
        for (int r = 0; r < 2; r++) {
            int idx  = tid + r * 256;
            int brow = idx >> 5;            // 0..15
            int bc4  = (idx & 31) << 2;     // 0..124
            float4 bv = *reinterpret_cast<const float4*>(
                Wbase + (size_t)(k0 + brow) * NHD + bc4);
            *reinterpret_cast<float4*>(&Bs[brow][bc4]) = bv;
        }
        __syncthreads();

        #pragma unroll
        for (int ks = 0; ks < 16; ks += 8) {
            wmma::fragment<wmma::matrix_a, 16, 16, 8, wmma::precision::tf32, wmma::row_major> afrag[2];
            wmma::fragment<wmma::matrix_b, 16, 16, 8, wmma::precision::tf32, wmma::row_major> bfrag[2];
            #pragma unroll
            for (int i = 0; i < 2; i++) {
                wmma::load_matrix_sync(afrag[i], &As[wm * 32 + i * 16][ks], 24);
                #pragma unroll
                for (int t = 0; t < afrag[i].num_elements; t++)
                    afrag[i].x[t] = wmma::__float_to_tf32(afrag[i].x[t]);
            }
            #pragma unroll
            for (int j = 0; j < 2; j++) {
                wmma::load_matrix_sync(bfrag[j], &Bs[ks][wn * 32 + j * 16], 136);
                #pragma unroll
                for (int t = 0; t < bfrag[j].num_elements; t++)
                    bfrag[j].x[t] = wmma::__float_to_tf32(bfrag[j].x[t]);
            }
            #pragma unroll
            for (int i = 0; i < 2; i++)
                #pragma unroll
                for (int j = 0; j < 2; j++)
                    wmma::mma_sync(acc[i][j], afrag[i], bfrag[j], acc[i][j]);
        }
        __syncthreads();
    }

    #pragma unroll
    for (int i = 0; i < 2; i++)
        #pragma unroll
        for (int j = 0; j < 2; j++) {
            int row = by * 64 + wm * 32 + i * 16;
            int col = bx * 128 + wn * 32 + j * 16;
            wmma::store_matrix_sync(&g_C[(size_t)row * KNN + col], acc[i][j],
                                    KNN, wmma::mem_row_major);
        }
}

// ---------------------------------------------------------------------------
// Kernel 2: block-local attention.
// One block per (b, n, h). Keys/values = 4 context rows (from g_C) + 16 block
// rows (from k/v). 16 queries. All tiles in smem; warp per pair of queries.
// ---------------------------------------------------------------------------
__global__ __launch_bounds__(256) void attn_kernel(
    const float* __restrict__ q,
    const float* __restrict__ k,
    const float* __restrict__ v,
    const int* __restrict__ mask,          // bool stored as int32 by harness
    float* __restrict__ out)
{
    const int bid = blockIdx.x;        // ((b*N + n)*NH + h)
    const int h  = bid & 15;
    const int bn = bid >> 4;
    const int n  = bn & 255;
    const int b  = bn >> 8;

    __shared__ float Qs[16][128];
    __shared__ float Ks[20][128];
    __shared__ float Vs[20][128];

    const int tid = threadIdx.x;

    // Base of q/k/v rows for this (b, n, h): row r at qbase + r*2048
    const size_t qbase = ((size_t)(b * (GN * BSQ) + n * BSQ) * NH + h) * DH;

    // Q tile: 16 rows x 128 = 512 float4
    for (int idx = tid; idx < 512; idx += 256) {
        int r = idx >> 5, c = (idx & 31) << 2;
        *reinterpret_cast<float4*>(&Qs[r][c]) =
            *reinterpret_cast<const float4*>(&q[qbase + (size_t)r * (NH * DH) + c]);
    }

    // K/V tiles: 20 rows x 128 = 640 float4 each
    const size_t cbase = (size_t)((b * GN + n) * GL) * KNN + (size_t)h * DH;
    for (int idx = tid; idx < 640; idx += 256) {
        int r = idx >> 5, c = (idx & 31) << 2;
        float4 kv4, vv4;
        if (r < GL) {
            kv4 = *reinterpret_cast<const float4*>(&g_C[cbase + (size_t)r * KNN + c]);
            vv4 = *reinterpret_cast<const float4*>(&g_C[cbase + (size_t)r * KNN + NHD + c]);
        } else {
            size_t off = qbase + (size_t)(r - GL) * (NH * DH) + c;
            kv4 = *reinterpret_cast<const float4*>(&k[off]);
            vv4 = *reinterpret_cast<const float4*>(&v[off]);
        }
        *reinterpret_cast<float4*>(&Ks[r][c]) = kv4;
        *reinterpret_cast<float4*>(&Vs[r][c]) = vv4;
    }
    __syncthreads();

    const int lane = tid & 31;
    const int warp = tid >> 5;
    const float keep = (mask[b * GN + n] != 0) ? 1.0f : 0.0f;

    for (int qi = warp; qi < 16; qi += 8) {
        float s[20];
        #pragma unroll
        for (int j = 0; j < 20; j++) {
            float acc = 0.0f;
            #pragma unroll
            for (int t = 0; t < 4; t++)
                acc += Qs[qi][lane + 32 * t] * Ks[j][lane + 32 * t];
            #pragma unroll
            for (int o = 16; o; o >>= 1)
                acc += __shfl_xor_sync(0xffffffff, acc, o);
            s[j] = acc * SCALE;
        }
        float mx = s[0];
        #pragma unroll
        for (int j = 1; j < 20; j++) mx = fmaxf(mx, s[j]);
        float sum = 0.0f;
        #pragma unroll
        for (int j = 0; j < 20; j++) { s[j] = __expf(s[j] - mx); sum += s[j]; }
        const float inv = keep / sum;

        float o0 = 0.f, o1 = 0.f, o2 = 0.f, o3 = 0.f;
        #pragma unroll
        for (int j = 0; j < 20; j++) {
            float p = s[j];
            o0 += p * Vs[j][lane];
            o1 += p * Vs[j][lane + 32];
            o2 += p * Vs[j][lane + 64];
            o3 += p * Vs[j][lane + 96];
        }
        const size_t obase =
            ((size_t)(b * (GN * BSQ) + n * BSQ + qi)) * NHD + (size_t)h * DH;
        out[obase + lane]       = o0 * inv;
        out[obase + lane + 32]  = o1 * inv;
        out[obase + lane + 64]  = o2 * inv;
        out[obase + lane + 96]  = o3 * inv;
    }
}

// ---------------------------------------------------------------------------
// kernel_launch
// Inputs (metadata order): hidden_states f32, anchor_positions (i32/i64),
// block_keep_mask (int32), q f32, k f32, v f32, W_kc f32, W_vc f32.
// Output: f32 (B, N*BS, NH*DH) = 16,777,216 elems.
// ---------------------------------------------------------------------------
extern "C" void kernel_launch(void* const* d_in, const int* in_sizes, int n_in,
                              void* d_out, int out_size)
{
    const float* hidden = (const float*)d_in[0];
    const void*  anchor = d_in[1];
    const int*   mask   = (const int*)d_in[2];
    const float* q      = (const float*)d_in[3];
    const float* k      = (const float*)d_in[4];
    const float* v      = (const float*)d_in[5];
    const float* Wkc    = (const float*)d_in[6];
    const float* Wvc    = (const float*)d_in[7];

    dim3 ggrid(KNN / 128, MM / 64);     // (32, 32)
    gemm_ctx_kernel<<<ggrid, 256>>>(hidden, anchor, Wkc, Wvc);

    attn_kernel<<<GB * GN * NH, 256>>>(q, k, v, mask, (float*)d_out);
}

// round 5
// speedup vs baseline: 1.0762x; 1.0762x over previous
#include <cuda_runtime.h>
#include <cuda_bf16.h>
#include <mma.h>

using namespace nvcuda;

// Problem constants
#define GB   2        // batch
#define GN   256      // num anchor blocks
#define GL   4        // layers
#define GS   4096     // seq len
#define GH   2048     // hidden
#define NH   16       // heads
#define DH   128      // head dim
#define BSQ  16       // block size (queries per anchor block)
#define NHD  2048     // NH*DH
#define MM   2048     // B*N*L rows of context GEMM
#define KNN  4096     // concat output cols (Wkc | Wvc)
#define SCALE 0.08838834764831845f  // 1/sqrt(128)

#define BM 128
#define BN 128
#define BK 16
#define NITER (GH / BK)   // 128

// Scratch: context GEMM output  C[m, 0:2048] = k_chs, C[m, 2048:4096] = v_chs
__device__ float g_C[(size_t)MM * KNN];

// Read anchor value regardless of whether the harness stored int32 or int64.
__device__ __forceinline__ bool anchor_is_i64(const void* anchor) {
    const long long* a64 = (const long long*)anchor;
    bool ok = true;
    #pragma unroll
    for (int i = 0; i < 4; i++) {
        long long t = a64[i];
        if (t < 0 || t >= GS) ok = false;
    }
    return ok;
}

__device__ __forceinline__ long long anchor_read(const void* anchor, int idx, bool is64) {
    if (is64) return ((const long long*)anchor)[idx];
    return (long long)((const int*)anchor)[idx];
}

__device__ __forceinline__ float4 tf32x4(float4 v) {
    v.x = wmma::__float_to_tf32(v.x);
    v.y = wmma::__float_to_tf32(v.y);
    v.z = wmma::__float_to_tf32(v.z);
    v.w = wmma::__float_to_tf32(v.w);
    return v;
}

// ---------------------------------------------------------------------------
// Kernel 1: gathered tf32 GEMM, 128x128x16 tiles, double-buffered smem,
// register prefetch, tf32 pre-rounding at smem store.
//   A[m,k] = hidden_states[l, b, ctx(b,n), k]  with m = ((b*N+n)*L + l)
//   Bmat   = [W_kc | W_vc]  (2048 x 4096), row-major
//   C      = A @ Bmat   (2048 x 4096)
// 8 warps: 2 (M) x 4 (N); each warp 64x32 = 4x2 wmma 16x16x8 tiles.
// ---------------------------------------------------------------------------
__global__ __launch_bounds__(256) void gemm_ctx_kernel(
    const float* __restrict__ hidden,
    const void* __restrict__ anchor,
    const float* __restrict__ Wkc,
    const float* __restrict__ Wvc)
{
    const int bx = blockIdx.x;   // output-col tile (128 wide): 0..31
    const int by = blockIdx.y;   // output-row tile (128 tall): 0..15
    const int tid = threadIdx.x;

    __shared__ float  As[2][BM][20];    // stride 20 (16B-aligned rows)
    __shared__ float  Bs[2][BK][136];
    __shared__ size_t rowbase[BM];

    if (tid < BM) {
        const bool is64 = anchor_is_i64(anchor);
        int m  = by * BM + tid;
        int l  = m & 3;
        int bn = m >> 2;
        int b  = bn >> 8;
        int n  = bn & 255;
        long long a = anchor_read(anchor, b * GN + n, is64) - 1;
        if (a < 0) a = 0;
        if (a > GS - 1) a = GS - 1;
        rowbase[tid] = (((size_t)l * GB + b) * GS + (size_t)a) * GH;
    }

    // A whole 128-wide col tile lives entirely in Wkc (bx<16) or Wvc.
    const float* Wbase = (bx < 16) ? (Wkc + bx * 128) : (Wvc + (bx - 16) * 128);

    wmma::fragment<wmma::accumulator, 16, 16, 8, float> acc[4][2];
    #pragma unroll
    for (int i = 0; i < 4; i++)
        #pragma unroll
        for (int j = 0; j < 2; j++)
            wmma::fill_fragment(acc[i][j], 0.0f);

    const int warp = tid >> 5;
    const int wm = warp & 1;      // 0..1 -> 64-row slice
    const int wn = warp >> 1;     // 0..3 -> 32-col slice

    __syncthreads();   // rowbase visible

    // Per-thread fixed load coordinates.
    // A: 128 rows x 16 cols = 512 float4; thread handles idx = tid, tid+256.
    const int arow = tid >> 2;               // 0..63 (and +64 for second)
    const int ac4  = (tid & 3) << 2;
    const float* aptr0 = hidden + rowbase[arow]      + ac4;
    const float* aptr1 = hidden + rowbase[arow + 64] + ac4;
    // B: 16 rows x 128 cols = 512 float4; thread handles brow, brow+8.
    const int brow = tid >> 5;               // 0..7
    const int bc4  = (tid & 31) << 2;
    const float* bptr0 = Wbase + (size_t)brow * NHD + bc4;
    const float* bptr1 = bptr0 + (size_t)8 * NHD;

    // Prologue: load tile 0 into buffer 0.
    {
        float4 a0 = tf32x4(*reinterpret_cast<const float4*>(aptr0));
        float4 a1 = tf32x4(*reinterpret_cast<const float4*>(aptr1));
        float4 b0 = tf32x4(*reinterpret_cast<const float4*>(bptr0));
        float4 b1 = tf32x4(*reinterpret_cast<const float4*>(bptr1));
        *reinterpret_cast<float4*>(&As[0][arow][ac4])      = a0;
        *reinterpret_cast<float4*>(&As[0][arow + 64][ac4]) = a1;
        *reinterpret_cast<float4*>(&Bs[0][brow][bc4])      = b0;
        *reinterpret_cast<float4*>(&Bs[0][brow + 8][bc4])  = b1;
    }
    __syncthreads();

    int buf = 0;
    for (int it = 0; it < NITER; it++) {
        float4 a0, a1, b0, b1;
        const bool has_next = (it + 1 < NITER);
        if (has_next) {
            const int k0 = (it + 1) * BK;
            a0 = *reinterpret_cast<const float4*>(aptr0 + k0);
            a1 = *reinterpret_cast<const float4*>(aptr1 + k0);
            b0 = *reinterpret_cast<const float4*>(bptr0 + (size_t)k0 * NHD);
            b1 = *reinterpret_cast<const float4*>(bptr1 + (size_t)k0 * NHD);
        }

        // Compute on current buffer (data already tf32-rounded).
        #pragma unroll
        for (int ks = 0; ks < BK; ks += 8) {
            wmma::fragment<wmma::matrix_a, 16, 16, 8, wmma::precision::tf32, wmma::row_major> af[4];
            wmma::fragment<wmma::matrix_b, 16, 16, 8, wmma::precision::tf32, wmma::row_major> bf[2];
            #pragma unroll
            for (int i = 0; i < 4; i++)
                wmma::load_matrix_sync(af[i], &As[buf][wm * 64 + i * 16][ks], 20);
            #pragma unroll
            for (int j = 0; j < 2; j++)
                wmma::load_matrix_sync(bf[j], &Bs[buf][ks][wn * 32 + j * 16], 136);
            #pragma unroll
            for (int i = 0; i < 4; i++)
                #pragma unroll
                for (int j = 0; j < 2; j++)
                    wmma::mma_sync(acc[i][j], af[i], bf[j], acc[i][j]);
        }

        if (has_next) {
            const int nb = buf ^ 1;
            *reinterpret_cast<float4*>(&As[nb][arow][ac4])      = tf32x4(a0);
            *reinterpret_cast<float4*>(&As[nb][arow + 64][ac4]) = tf32x4(a1);
            *reinterpret_cast<float4*>(&Bs[nb][brow][bc4])      = tf32x4(b0);
            *reinterpret_cast<float4*>(&Bs[nb][brow + 8][bc4])  = tf32x4(b1);
            __syncthreads();
            buf = nb;
        }
    }

    #pragma unroll
    for (int i = 0; i < 4; i++)
        #pragma unroll
        for (int j = 0; j < 2; j++) {
            int row = by * BM + wm * 64 + i * 16;
            int col = bx * BN + wn * 32 + j * 16;
            wmma::store_matrix_sync(&g_C[(size_t)row * KNN + col], acc[i][j],
                                    KNN, wmma::mem_row_major);
        }
}

// ---------------------------------------------------------------------------
// Kernel 2: block-local attention.
// One block per (b, n, h). Keys/values = 4 context rows (from g_C) + 16 block
// rows (from k/v). 16 queries. All tiles in smem; warp per pair of queries.
// ---------------------------------------------------------------------------
__global__ __launch_bounds__(256) void attn_kernel(
    const float* __restrict__ q,
    const float* __restrict__ k,
    const float* __restrict__ v,
    const int* __restrict__ mask,          // bool stored as int32 by harness
    float* __restrict__ out)
{
    const int bid = blockIdx.x;        // ((b*N + n)*NH + h)
    const int h  = bid & 15;
    const int bn = bid >> 4;
    const int n  = bn & 255;
    const int b  = bn >> 8;

    __shared__ float Qs[16][128];
    __shared__ float Ks[20][128];
    __shared__ float Vs[20][128];

    const int tid = threadIdx.x;

    // Base of q/k/v rows for this (b, n, h): row r at qbase + r*2048
    const size_t qbase = ((size_t)(b * (GN * BSQ) + n * BSQ) * NH + h) * DH;

    // Q tile: 16 rows x 128 = 512 float4
    for (int idx = tid; idx < 512; idx += 256) {
        int r = idx >> 5, c = (idx & 31) << 2;
        *reinterpret_cast<float4*>(&Qs[r][c]) =
            *reinterpret_cast<const float4*>(&q[qbase + (size_t)r * (NH * DH) + c]);
    }

    // K/V tiles: 20 rows x 128 = 640 float4 each
    const size_t cbase = (size_t)((b * GN + n) * GL) * KNN + (size_t)h * DH;
    for (int idx = tid; idx < 640; idx += 256) {
        int r = idx >> 5, c = (idx & 31) << 2;
        float4 kv4, vv4;
        if (r < GL) {
            kv4 = *reinterpret_cast<const float4*>(&g_C[cbase + (size_t)r * KNN + c]);
            vv4 = *reinterpret_cast<const float4*>(&g_C[cbase + (size_t)r * KNN + NHD + c]);
        } else {
            size_t off = qbase + (size_t)(r - GL) * (NH * DH) + c;
            kv4 = *reinterpret_cast<const float4*>(&k[off]);
            vv4 = *reinterpret_cast<const float4*>(&v[off]);
        }
        *reinterpret_cast<float4*>(&Ks[r][c]) = kv4;
        *reinterpret_cast<float4*>(&Vs[r][c]) = vv4;
    }
    __syncthreads();

    const int lane = tid & 31;
    const int warp = tid >> 5;
    const float keep = (mask[b * GN + n] != 0) ? 1.0f : 0.0f;

    for (int qi = warp; qi < 16; qi += 8) {
        // Hoist Q row slice into registers (reused across all 20 keys).
        float q0 = Qs[qi][lane];
        float q1 = Qs[qi][lane + 32];
        float q2 = Qs[qi][lane + 64];
        float q3 = Qs[qi][lane + 96];

        float s[20];
        #pragma unroll
        for (int j = 0; j < 20; j++) {
            float acc = q0 * Ks[j][lane]
                      + q1 * Ks[j][lane + 32]
                      + q2 * Ks[j][lane + 64]
                      + q3 * Ks[j][lane + 96];
            #pragma unroll
            for (int o = 16; o; o >>= 1)
                acc += __shfl_xor_sync(0xffffffff, acc, o);
            s[j] = acc * SCALE;
        }
        float mx = s[0];
        #pragma unroll
        for (int j = 1; j < 20; j++) mx = fmaxf(mx, s[j]);
        float sum = 0.0f;
        #pragma unroll
        for (int j = 0; j < 20; j++) { s[j] = __expf(s[j] - mx); sum += s[j]; }
        const float inv = keep / sum;

        float o0 = 0.f, o1 = 0.f, o2 = 0.f, o3 = 0.f;
        #pragma unroll
        for (int j = 0; j < 20; j++) {
            float p = s[j];
            o0 += p * Vs[j][lane];
            o1 += p * Vs[j][lane + 32];
            o2 += p * Vs[j][lane + 64];
            o3 += p * Vs[j][lane + 96];
        }
        const size_t obase =
            ((size_t)(b * (GN * BSQ) + n * BSQ + qi)) * NHD + (size_t)h * DH;
        out[obase + lane]       = o0 * inv;
        out[obase + lane + 32]  = o1 * inv;
        out[obase + lane + 64]  = o2 * inv;
        out[obase + lane + 96]  = o3 * inv;
    }
}

// ---------------------------------------------------------------------------
// kernel_launch
// Inputs (metadata order): hidden_states f32, anchor_positions (i32/i64),
// block_keep_mask (int32), q f32, k f32, v f32, W_kc f32, W_vc f32.
// Output: f32 (B, N*BS, NH*DH) = 16,777,216 elems.
// ---------------------------------------------------------------------------
extern "C" void kernel_launch(void* const* d_in, const int* in_sizes, int n_in,
                              void* d_out, int out_size)
{
    const float* hidden = (const float*)d_in[0];
    const void*  anchor = d_in[1];
    const int*   mask   = (const int*)d_in[2];
    const float* q      = (const float*)d_in[3];
    const float* k      = (const float*)d_in[4];
    const float* v      = (const float*)d_in[5];
    const float* Wkc    = (const float*)d_in[6];
    const float* Wvc    = (const float*)d_in[7];

    dim3 ggrid(KNN / BN, MM / BM);     // (32, 16)
    gemm_ctx_kernel<<<ggrid, 256>>>(hidden, anchor, Wkc, Wvc);

    attn_kernel<<<GB * GN * NH, 256>>>(q, k, v, mask, (float*)d_out);
}

// round 8
// speedup vs baseline: 1.6657x; 1.5478x over previous
#include <cuda_runtime.h>
#include <cuda_bf16.h>
#include <cstdint>

// Problem constants
#define GB   2
#define GN   256
#define GL   4
#define GS   4096
#define GH   2048      // K of context GEMM
#define NH   16
#define DH   128
#define BSQ  16
#define NHD  2048
#define MM   2048      // B*N*L rows
#define KNN  4096      // [Wkc | Wvc] output cols
#define SCALE 0.08838834764831845f

// GEMM tiling: block 128x128, 4 warps (2x2), warp tile 64x64, K staged 16.
#define KC     16
#define NITER  (GH / KC)      // 128
#define ASTRIDE 20            // floats; 20*qp+qc mod 32 covers all banks
#define STAGE_F (128 * ASTRIDE)   // floats per stage per operand (2560)

// Scratch
__device__ float g_C[(size_t)MM * KNN];     // context GEMM out: [m][kcols|vcols]
__device__ float g_WT[(size_t)KNN * GH];    // W transposed: [n][k]

// ---------------------------------------------------------------------------
// helpers
// ---------------------------------------------------------------------------
__device__ __forceinline__ uint32_t smem_u32(const void* p) {
    uint32_t a;
    asm("{ .reg .u64 t; cvta.to.shared.u64 t, %1; cvt.u32.u64 %0, t; }" : "=r"(a) : "l"(p));
    return a;
}
__device__ __forceinline__ void cp_async16(uint32_t dst, const void* src) {
    asm volatile("cp.async.cg.shared.global [%0], [%1], 16;" :: "r"(dst), "l"(src) : "memory");
}
__device__ __forceinline__ void cp_commit() {
    asm volatile("cp.async.commit_group;" ::: "memory");
}
__device__ __forceinline__ void cp_wait1() {
    asm volatile("cp.async.wait_group 1;" ::: "memory");
}
__device__ __forceinline__ void mma_tf32(float* c, const uint32_t* a, const uint32_t* b) {
    asm volatile(
        "mma.sync.aligned.m16n8k8.row.col.f32.tf32.tf32.f32 "
        "{%0,%1,%2,%3}, {%4,%5,%6,%7}, {%8,%9}, {%0,%1,%2,%3};"
        : "+f"(c[0]), "+f"(c[1]), "+f"(c[2]), "+f"(c[3])
        : "r"(a[0]), "r"(a[1]), "r"(a[2]), "r"(a[3]), "r"(b[0]), "r"(b[1]));
}

// Anchor dtype handling (harness may store int32 or int64)
__device__ __forceinline__ bool anchor_is_i64(const void* anchor) {
    const long long* a64 = (const long long*)anchor;
    bool ok = true;
    #pragma unroll
    for (int i = 0; i < 4; i++) {
        long long t = a64[i];
        if (t < 0 || t >= GS) ok = false;
    }
    return ok;
}
__device__ __forceinline__ long long anchor_read(const void* anchor, int idx, bool is64) {
    if (is64) return ((const long long*)anchor)[idx];
    return (long long)((const int*)anchor)[idx];
}

// ---------------------------------------------------------------------------
// Kernel 0: transpose [Wkc | Wvc] (2048 x 2048 each, row-major) -> g_WT [n][k]
// ---------------------------------------------------------------------------
__global__ __launch_bounds__(256) void transpose_w_kernel(
    const float* __restrict__ Wkc, const float* __restrict__ Wvc)
{
    __shared__ float t[32][33];
    const int kb = blockIdx.x * 32;
    const int nb = blockIdx.y * 32;   // global n, 0..4095
    const float* W = (nb < NHD) ? Wkc : Wvc;
    const int nloc = (nb < NHD) ? nb : nb - NHD;
    const int tx = threadIdx.x & 31, ty = threadIdx.x >> 5;
    #pragma unroll
    for (int j = 0; j < 4; j++)
        t[ty + 8 * j][tx] = W[(size_t)(kb + ty + 8 * j) * NHD + nloc + tx];
    __syncthreads();
    #pragma unroll
    for (int j = 0; j < 4; j++)
        g_WT[(size_t)(nb + ty + 8 * j) * GH + kb + tx] = t[tx][ty + 8 * j];
}

// ---------------------------------------------------------------------------
// Kernel 1: gathered tf32 GEMM via raw mma.sync.m16n8k8 + cp.async pipeline.
//   C[m][n] = sum_k hid_gather[m][k] * g_WT[n][k]
//   Block 128x128, 4 warps, warp tile 64x64, 2-stage cp.async.
// ---------------------------------------------------------------------------
__global__ __launch_bounds__(128, 2) void gemm_mma_kernel(
    const float* __restrict__ hidden,
    const void* __restrict__ anchor)
{
    __shared__ __align__(16) float As[2][128][ASTRIDE];
    __shared__ __align__(16) float Bs[2][128][ASTRIDE];
    __shared__ size_t rowb[128];

    const int tid = threadIdx.x;
    const int bx = blockIdx.x;   // N tile 0..31
    const int by = blockIdx.y;   // M tile 0..15

    if (tid < 128) {
        const bool is64 = anchor_is_i64(anchor);
        int m = by * 128 + tid;
        int l = m & 3, bn = m >> 2, b = bn >> 8, n = bn & 255;
        long long a = anchor_read(anchor, b * GN + n, is64) - 1;
        if (a < 0) a = 0;
        if (a > GS - 1) a = GS - 1;
        rowb[tid] = (((size_t)l * GB + b) * GS + (size_t)a) * GH;
    }
    __syncthreads();

    // cp.async coordinates: 1024 16B-chunks per stage (512 A + 512 B),
    // 8 per thread. Rows r0 + {0,32,64,96} for each of A and B.
    const int r0 = tid >> 2;
    const int c4 = (tid & 3) << 2;
    const float* aS[4];
    const float* bS[4];
    uint32_t aD[4], bD[4];
    #pragma unroll
    for (int j = 0; j < 4; j++) {
        aS[j] = hidden + rowb[r0 + 32 * j] + c4;
        bS[j] = g_WT + (size_t)(bx * 128 + r0 + 32 * j) * GH + c4;
        aD[j] = smem_u32(&As[0][r0 + 32 * j][c4]);
        bD[j] = smem_u32(&Bs[0][r0 + 32 * j][c4]);
    }
    const uint32_t stage_b = STAGE_F * 4;   // bytes per stage

    // accumulators: warp 64x64 -> 4 m16 x 8 n8 tiles, 4 regs each
    float acc[4][8][4];
    #pragma unroll
    for (int mi = 0; mi < 4; mi++)
        #pragma unroll
        for (int ni = 0; ni < 8; ni++)
            #pragma unroll
            for (int r = 0; r < 4; r++)
                acc[mi][ni][r] = 0.0f;

    const int lane = tid & 31;
    const int warp = tid >> 5;
    const int qp = lane >> 2;        // groupID
    const int qc = lane & 3;         // threadID-in-group
    const int wm = warp & 1;         // M half
    const int wn = warp >> 1;        // N half

    // prologue: stages 0,1
    #pragma unroll
    for (int s = 0; s < 2; s++) {
        const int k0 = s * KC;
        const uint32_t so = s * stage_b;
        #pragma unroll
        for (int j = 0; j < 4; j++) {
            cp_async16(aD[j] + so, aS[j] + k0);
            cp_async16(bD[j] + so, bS[j] + k0);
        }
        cp_commit();
    }

    for (int it = 0; it < NITER; it++) {
        cp_wait1();
        __syncthreads();

        const int buf = it & 1;
        #pragma unroll
        for (int ks = 0; ks < KC; ks += 8) {
            uint32_t a[4][4], b[8][2];
            #pragma unroll
            for (int mi = 0; mi < 4; mi++) {
                const int row = wm * 64 + mi * 16 + qp;
                a[mi][0] = __float_as_uint(As[buf][row][ks + qc]);
                a[mi][1] = __float_as_uint(As[buf][row + 8][ks + qc]);
                a[mi][2] = __float_as_uint(As[buf][row][ks + qc + 4]);
                a[mi][3] = __float_as_uint(As[buf][row + 8][ks + qc + 4]);
            }
            #pragma unroll
            for (int ni = 0; ni < 8; ni++) {
                const int rn = wn * 64 + ni * 8 + qp;
                b[ni][0] = __float_as_uint(Bs[buf][rn][ks + qc]);
                b[ni][1] = __float_as_uint(Bs[buf][rn][ks + qc + 4]);
            }
            #pragma unroll
            for (int mi = 0; mi < 4; mi++)
                #pragma unroll
                for (int ni = 0; ni < 8; ni++)
                    mma_tf32(acc[mi][ni], a[mi], b[ni]);
        }

        __syncthreads();   // all warps done reading buf before refilling it

        const int nxt = it + 2;
        if (nxt < NITER) {
            const int k0 = nxt * KC;
            const uint32_t so = (nxt & 1) * stage_b;
            #pragma unroll
            for (int j = 0; j < 4; j++) {
                cp_async16(aD[j] + so, aS[j] + k0);
                cp_async16(bD[j] + so, bS[j] + k0);
            }
        }
        cp_commit();   // unconditional: keeps group accounting uniform
    }

    // epilogue: c0,c1 at (row, col..col+1), c2,c3 at (row+8, col..col+1)
    #pragma unroll
    for (int mi = 0; mi < 4; mi++) {
        const int row = by * 128 + wm * 64 + mi * 16 + qp;
        #pragma unroll
        for (int ni = 0; ni < 8; ni++) {
            const int col = bx * 128 + wn * 64 + ni * 8 + 2 * qc;
            *reinterpret_cast<float2*>(&g_C[(size_t)row * KNN + col]) =
                make_float2(acc[mi][ni][0], acc[mi][ni][1]);
            *reinterpret_cast<float2*>(&g_C[(size_t)(row + 8) * KNN + col]) =
                make_float2(acc[mi][ni][2], acc[mi][ni][3]);
        }
    }
}

// ---------------------------------------------------------------------------
// Kernel 2: block-local attention (unchanged; ~146 us)
// ---------------------------------------------------------------------------
__global__ __launch_bounds__(256) void attn_kernel(
    const float* __restrict__ q,
    const float* __restrict__ k,
    const float* __restrict__ v,
    const int* __restrict__ mask,
    float* __restrict__ out)
{
    const int bid = blockIdx.x;
    const int h  = bid & 15;
    const int bn = bid >> 4;
    const int n  = bn & 255;
    const int b  = bn >> 8;

    __shared__ float Qs[16][128];
    __shared__ float Ks[20][128];
    __shared__ float Vs[20][128];

    const int tid = threadIdx.x;
    const size_t qbase = ((size_t)(b * (GN * BSQ) + n * BSQ) * NH + h) * DH;

    for (int idx = tid; idx < 512; idx += 256) {
        int r = idx >> 5, c = (idx & 31) << 2;
        *reinterpret_cast<float4*>(&Qs[r][c]) =
            *reinterpret_cast<const float4*>(&q[qbase + (size_t)r * NHD + c]);
    }
    const size_t cbase = (size_t)((b * GN + n) * GL) * KNN + (size_t)h * DH;
    for (int idx = tid; idx < 640; idx += 256) {
        int r = idx >> 5, c = (idx & 31) << 2;
        float4 kv4, vv4;
        if (r < GL) {
            kv4 = *reinterpret_cast<const float4*>(&g_C[cbase + (size_t)r * KNN + c]);
            vv4 = *reinterpret_cast<const float4*>(&g_C[cbase + (size_t)r * KNN + NHD + c]);
        } else {
            size_t off = qbase + (size_t)(r - GL) * NHD + c;
            kv4 = *reinterpret_cast<const float4*>(&k[off]);
            vv4 = *reinterpret_cast<const float4*>(&v[off]);
        }
        *reinterpret_cast<float4*>(&Ks[r][c]) = kv4;
        *reinterpret_cast<float4*>(&Vs[r][c]) = vv4;
    }
    __syncthreads();

    const int lane = tid & 31;
    const int warp = tid >> 5;
    const float keep = (mask[b * GN + n] != 0) ? 1.0f : 0.0f;

    for (int qi = warp; qi < 16; qi += 8) {
        float q0 = Qs[qi][lane];
        float q1 = Qs[qi][lane + 32];
        float q2 = Qs[qi][lane + 64];
        float q3 = Qs[qi][lane + 96];

        float s[20];
        #pragma unroll
        for (int j = 0; j < 20; j++) {
            float acc = q0 * Ks[j][lane] + q1 * Ks[j][lane + 32]
                      + q2 * Ks[j][lane + 64] + q3 * Ks[j][lane + 96];
            #pragma unroll
            for (int o = 16; o; o >>= 1)
                acc += __shfl_xor_sync(0xffffffff, acc, o);
            s[j] = acc * SCALE;
        }
        float mx = s[0];
        #pragma unroll
        for (int j = 1; j < 20; j++) mx = fmaxf(mx, s[j]);
        float sum = 0.0f;
        #pragma unroll
        for (int j = 0; j < 20; j++) { s[j] = __expf(s[j] - mx); sum += s[j]; }
        const float inv = keep / sum;

        float o0 = 0.f, o1 = 0.f, o2 = 0.f, o3 = 0.f;
        #pragma unroll
        for (int j = 0; j < 20; j++) {
            float p = s[j];
            o0 += p * Vs[j][lane];
            o1 += p * Vs[j][lane + 32];
            o2 += p * Vs[j][lane + 64];
            o3 += p * Vs[j][lane + 96];
        }
        const size_t obase =
            ((size_t)(b * (GN * BSQ) + n * BSQ + qi)) * NHD + (size_t)h * DH;
        out[obase + lane]       = o0 * inv;
        out[obase + lane + 32]  = o1 * inv;
        out[obase + lane + 64]  = o2 * inv;
        out[obase + lane + 96]  = o3 * inv;
    }
}

// ---------------------------------------------------------------------------
// kernel_launch
// ---------------------------------------------------------------------------
extern "C" void kernel_launch(void* const* d_in, const int* in_sizes, int n_in,
                              void* d_out, int out_size)
{
    const float* hidden = (const float*)d_in[0];
    const void*  anchor = d_in[1];
    const int*   mask   = (const int*)d_in[2];
    const float* q      = (const float*)d_in[3];
    const float* k      = (const float*)d_in[4];
    const float* v      = (const float*)d_in[5];
    const float* Wkc    = (const float*)d_in[6];
    const float* Wvc    = (const float*)d_in[7];

    dim3 tgrid(GH / 32, KNN / 32);   // (64, 128)
    transpose_w_kernel<<<tgrid, 256>>>(Wkc, Wvc);

    dim3 ggrid(KNN / 128, MM / 128); // (32, 16)
    gemm_mma_kernel<<<ggrid, 128>>>(hidden, anchor);

    attn_kernel<<<GB * GN * NH, 256>>>(q, k, v, mask, (float*)d_out);
}